// round 8
// baseline (speedup 1.0000x reference)
#include <cuda_runtime.h>

#define LOG2E 1.4426950408889634f
#define N_EN  20000
#define M_MEN 256
#define TN 64   // entities per block (threadIdx.x)
#define MG 4    // mention-groups per block (threadIdx.y)
#define RM 8    // mentions per thread

typedef unsigned long long ull;

__device__ __forceinline__ float ex2f(float x){float r;asm("ex2.approx.ftz.f32 %0,%1;":"=f"(r):"f"(x));return r;}
__device__ __forceinline__ float lg2f(float x){float r;asm("lg2.approx.ftz.f32 %0,%1;":"=f"(r):"f"(x));return r;}

__device__ __forceinline__ ull pk(float a,float b){ull r;asm("mov.b64 %0,{%1,%2};":"=l"(r):"f"(a),"f"(b));return r;}
__device__ __forceinline__ void upk(ull v,float&a,float&b){asm("mov.b64 {%0,%1},%2;":"=f"(a),"=f"(b):"l"(v));}
__device__ __forceinline__ ull ffma2(ull a,ull b,ull c){ull r;asm("fma.rn.f32x2 %0,%1,%2,%3;":"=l"(r):"l"(a),"l"(b),"l"(c));return r;}
__device__ __forceinline__ ull fmul2(ull a,ull b){ull r;asm("mul.rn.f32x2 %0,%1,%2;":"=l"(r):"l"(a),"l"(b));return r;}
__device__ __forceinline__ ull fadd2(ull a,ull b){ull r;asm("add.rn.f32x2 %0,%1,%2;":"=l"(r):"l"(a),"l"(b));return r;}

// Deg-6 poly for ln(1+t) on [0,1] (closed-form Chebyshev, z=3-2*sqrt2).
// b0=2.66e-6 > 0 keeps chunk products positive. Evaluated Estrin-style
// (even/odd in t^2): same op count as Horner, 24-cyc chain vs 32.
struct PolyC { ull b6,b5,b4,b3,b2,b1,b0,ln2; };

// softplus (nats) for a packed pair y = (y0,y1), y = x*log2e.
__device__ __forceinline__ ull sp_pair(ull y, const PolyC& C){
    float y0, y1; upk(y, y0, y1);
    float t0 = ex2f(-fabsf(y0));
    float t1 = ex2f(-fabsf(y1));
    float r0 = fmaxf(y0, 0.f);
    float r1 = fmaxf(y1, 0.f);
    ull tv = pk(t0,t1);
    ull rv = pk(r0,r1);
    ull t2 = fmul2(tv, tv);
    ull E  = ffma2(C.b6, t2, C.b4);
    E      = ffma2(E,  t2, C.b2);
    E      = ffma2(E,  t2, C.b0);
    ull O  = ffma2(C.b5, t2, C.b3);
    O      = ffma2(O,  t2, C.b1);
    ull P  = ffma2(O, tv, E);        // ln(1+t) > 0
    return ffma2(rv, C.ln2, P);      // relu*ln2 + P
}

// lg2( prod_{d in chunk of 8} softplus( min(mZ,eZ) + min(-mz,-ez) ) )
// mzn: NEGATED scaled mention mins; ezn: NEGATED scaled entity mins.
__device__ __forceinline__ float chunk_lg2(const float* mzn, const float* mZ,
                                           const float* ezn, const float* eZ,
                                           const PolyC& C){
    ull prod = 0;
#pragma unroll
    for (int p = 0; p < 4; ++p){
        float h0 = fminf(mZ[2*p],    eZ[2*p]);
        float h1 = fminf(mZ[2*p+1],  eZ[2*p+1]);
        float l0 = fminf(mzn[2*p],   ezn[2*p]);    // = -max(mz,ez)
        float l1 = fminf(mzn[2*p+1], ezn[2*p+1]);
        ull y = fadd2(pk(h0,h1), pk(l0,l1));       // hi - lo, packed
        ull s = sp_pair(y, C);
        prod = p ? fmul2(prod, s) : s;
    }
    float pa, pb; upk(prod, pa, pb);
    return lg2f(pa * pb);
}

__device__ __forceinline__ void load8(const float* p, float* v){
    float4 a = *(const float4*)p;
    float4 b = *(const float4*)(p + 4);
    v[0]=a.x; v[1]=a.y; v[2]=a.z; v[3]=a.w;
    v[4]=b.x; v[5]=b.y; v[6]=b.z; v[7]=b.w;
}
__device__ __forceinline__ void load8sc(const float* p, float* v, float scale){
    float4 a = *(const float4*)p;
    float4 b = *(const float4*)(p + 4);
    v[0]=a.x*scale; v[1]=a.y*scale; v[2]=a.z*scale; v[3]=a.w*scale;
    v[4]=b.x*scale; v[5]=b.y*scale; v[6]=b.z*scale; v[7]=b.w*scale;
}

__global__ __launch_bounds__(256, 3) void ivr_kernel(const float* __restrict__ men,
                                                     const float* __restrict__ en,
                                                     float* __restrict__ out){
    __shared__ float s_men[32][128];   // cols 0-63: -z*log2e ; cols 64-127: Z*log2e
    __shared__ float s_gmp[256];
    __shared__ float s_gm[32];

    PolyC C;
    C.b6  = pk(-0.017415424f, -0.017415424f);
    C.b5  = pk( 0.08269552f,   0.08269552f);
    C.b4  = pk(-0.190359232f, -0.190359232f);
    C.b3  = pk( 0.31574968f,   0.31574968f);
    C.b2  = pk(-0.497373624f, -0.497373624f);
    C.b1  = pk( 0.9998477f,    0.9998477f);
    C.b0  = pk( 2.66e-6f,      2.66e-6f);
    C.ln2 = pk( 0.69314718f,   0.69314718f);

    const int tid = threadIdx.y * TN + threadIdx.x;
    const int m0  = blockIdx.y * 32;

#pragma unroll
    for (int i = 0; i < 16; ++i){
        int idx = tid + i * 256;
        float sc = (idx & 64) ? LOG2E : -LOG2E;    // negate mins, keep maxs
        s_men[idx >> 7][idx & 127] = men[m0 * 128 + idx] * sc;
    }
    __syncthreads();

    // per-mention self volume (identical value path -> approx error cancels)
    {
        int mi = tid >> 3, ci = tid & 7;
        float mzn[8], mZv[8];
        load8(&s_men[mi][ci*8],      mzn);
        load8(&s_men[mi][64 + ci*8], mZv);
        s_gmp[tid] = chunk_lg2(mzn, mZv, mzn, mZv, C);
    }
    __syncthreads();
    if (tid < 32){
        float s = 0.f;
#pragma unroll
        for (int i = 0; i < 8; ++i) s += s_gmp[tid*8 + i];
        s_gm[tid] = s;
    }
    __syncthreads();

    const int n = blockIdx.x * TN + threadIdx.x;
    if (n >= N_EN) return;

    const int mg = threadIdx.y;
    float acc[RM];
#pragma unroll
    for (int j = 0; j < RM; ++j) acc[j] = 0.f;

    const float* erow = en + (size_t)n * 128;

#pragma unroll 2
    for (int c = 0; c < 8; ++c){
        float ezn[8], eZ[8];
        load8sc(erow + c*8,      ezn, -LOG2E);   // negated scaled mins
        load8sc(erow + 64 + c*8, eZ,   LOG2E);

#pragma unroll
        for (int j = 0; j < RM; ++j){
            float mzn[8], mZv[8];
            load8(&s_men[mg*RM + j][c*8],      mzn);   // smem broadcast
            load8(&s_men[mg*RM + j][64 + c*8], mZv);
            acc[j] += chunk_lg2(mzn, mZv, ezn, eZ, C);
        }
    }

#pragma unroll
    for (int j = 0; j < RM; ++j){
        int m = m0 + mg*RM + j;
        out[(size_t)m * N_EN + n] = ex2f(acc[j] - s_gm[mg*RM + j]);
    }
}

extern "C" void kernel_launch(void* const* d_in, const int* in_sizes, int n_in,
                              void* d_out, int out_size){
    const float* men = (const float*)d_in[0];
    const float* en  = (const float*)d_in[1];
    if (n_in >= 2 && in_sizes[0] > in_sizes[1]){
        const float* t = men; men = en; en = t;
    }
    float* out = (float*)d_out;

    dim3 block(TN, MG);
    dim3 grid((N_EN + TN - 1) / TN, M_MEN / (MG * RM));
    ivr_kernel<<<grid, block>>>(men, en, out);
}

// round 9
// speedup vs baseline: 1.1650x; 1.1650x over previous
#include <cuda_runtime.h>

#define LOG2E 1.4426950408889634f
#define N_EN  20000
#define M_MEN 256
#define TN 64   // entities per block (threadIdx.x)
#define MG 4    // mention-groups per block (threadIdx.y)
#define RM 8    // mentions per thread

typedef unsigned long long ull;

__device__ __forceinline__ float ex2f(float x){float r;asm("ex2.approx.ftz.f32 %0,%1;":"=f"(r):"f"(x));return r;}
__device__ __forceinline__ float lg2f(float x){float r;asm("lg2.approx.ftz.f32 %0,%1;":"=f"(r):"f"(x));return r;}

__device__ __forceinline__ ull pk(float a,float b){ull r;asm("mov.b64 %0,{%1,%2};":"=l"(r):"f"(a),"f"(b));return r;}
__device__ __forceinline__ void upk(ull v,float&a,float&b){asm("mov.b64 {%0,%1},%2;":"=f"(a),"=f"(b):"l"(v));}
__device__ __forceinline__ ull ffma2(ull a,ull b,ull c){ull r;asm("fma.rn.f32x2 %0,%1,%2,%3;":"=l"(r):"l"(a),"l"(b),"l"(c));return r;}
__device__ __forceinline__ ull fmul2(ull a,ull b){ull r;asm("mul.rn.f32x2 %0,%1,%2;":"=l"(r):"l"(a),"l"(b));return r;}
__device__ __forceinline__ ull fadd2(ull a,ull b){ull r;asm("add.rn.f32x2 %0,%1,%2;":"=l"(r):"l"(a),"l"(b));return r;}

// Deg-6 poly Q(t) ~= log2(1+t) on [0,1]  (= P(t)/ln2, closed-form Chebyshev).
// Q(0)=3.84e-6 > 0 keeps chunk products positive.
struct PolyC { ull b6,b5,b4,b3,b2,b1,b0; };

// One 8-dim chunk: returns lg2( prod_d v_d ), v_d = log2(1 + 2^{y_d}),
// y = min(mZ,eZ) - max(mz,ez)  (inputs prescaled by log2e).
// dims 0-3: MUFU path (v = lg2(1+ex2(y)))  -- runs on the MUFU pipe
// dims 4-7: poly path (v = relu(y) + Q(2^-|y|)) -- runs on the fma pipe
__device__ __forceinline__ float chunk_lg2(const float* mz, const float* mZ,
                                           const float* ez, const float* eZ,
                                           const PolyC& C){
    float va[4];
#pragma unroll
    for (int d = 0; d < 4; ++d){
        float y = fminf(mZ[d], eZ[d]) - fmaxf(mz[d], ez[d]);
        va[d] = lg2f(1.f + ex2f(y));
    }
    ull vb[2];
#pragma unroll
    for (int p = 0; p < 2; ++p){
        float y0 = fminf(mZ[4+2*p], eZ[4+2*p]) - fmaxf(mz[4+2*p], ez[4+2*p]);
        float y1 = fminf(mZ[5+2*p], eZ[5+2*p]) - fmaxf(mz[5+2*p], ez[5+2*p]);
        float t0 = ex2f(-fabsf(y0));
        float t1 = ex2f(-fabsf(y1));
        ull tv = pk(t0, t1);
        ull rv = pk(fmaxf(y0, 0.f), fmaxf(y1, 0.f));
        ull q = ffma2(C.b6, tv, C.b5);
        q = ffma2(q, tv, C.b4);
        q = ffma2(q, tv, C.b3);
        q = ffma2(q, tv, C.b2);
        q = ffma2(q, tv, C.b1);
        q = ffma2(q, tv, C.b0);       // Q(t) ~= log2(1+t) > 0
        vb[p] = fadd2(rv, q);         // v = relu(y) + Q(t)
    }
    ull prod = fmul2(fmul2(pk(va[0], va[1]), pk(va[2], va[3])),
                     fmul2(vb[0], vb[1]));
    float pa, pb; upk(prod, pa, pb);
    return lg2f(pa * pb);
}

__device__ __forceinline__ void load8(const float* p, float* v){
    float4 a = *(const float4*)p;
    float4 b = *(const float4*)(p + 4);
    v[0]=a.x; v[1]=a.y; v[2]=a.z; v[3]=a.w;
    v[4]=b.x; v[5]=b.y; v[6]=b.z; v[7]=b.w;
}
__device__ __forceinline__ void load8s(const float* p, float* v){
    float4 a = *(const float4*)p;
    float4 b = *(const float4*)(p + 4);
    v[0]=a.x*LOG2E; v[1]=a.y*LOG2E; v[2]=a.z*LOG2E; v[3]=a.w*LOG2E;
    v[4]=b.x*LOG2E; v[5]=b.y*LOG2E; v[6]=b.z*LOG2E; v[7]=b.w*LOG2E;
}

__global__ __launch_bounds__(256, 3) void ivr_kernel(const float* __restrict__ men,
                                                     const float* __restrict__ en,
                                                     float* __restrict__ out){
    __shared__ float s_men[32][128];   // 32 mentions, prescaled by log2e
    __shared__ float s_gmp[256];
    __shared__ float s_gm[32];

    PolyC C;
    C.b6 = pk(-0.02512518f, -0.02512518f);
    C.b5 = pk( 0.1193046f,   0.1193046f);
    C.b4 = pk(-0.2746312f,  -0.2746312f);
    C.b3 = pk( 0.4555314f,   0.4555314f);
    C.b2 = pk(-0.7175598f,  -0.7175598f);
    C.b1 = pk( 1.4424753f,   1.4424753f);
    C.b0 = pk( 3.84e-6f,     3.84e-6f);

    const int tid = threadIdx.y * TN + threadIdx.x;
    const int m0  = blockIdx.y * 32;

#pragma unroll
    for (int i = 0; i < 16; ++i){
        int idx = tid + i * 256;
        s_men[idx >> 7][idx & 127] = men[m0 * 128 + idx] * LOG2E;
    }
    __syncthreads();

    // per-mention self volume (identical value path -> approx error cancels)
    {
        int mi = tid >> 3, ci = tid & 7;
        float mzv[8], mZv[8];
        load8(&s_men[mi][ci*8],      mzv);
        load8(&s_men[mi][64 + ci*8], mZv);
        s_gmp[tid] = chunk_lg2(mzv, mZv, mzv, mZv, C);
    }
    __syncthreads();
    if (tid < 32){
        float s = 0.f;
#pragma unroll
        for (int i = 0; i < 8; ++i) s += s_gmp[tid*8 + i];
        s_gm[tid] = s;
    }
    __syncthreads();

    const int n = blockIdx.x * TN + threadIdx.x;
    if (n >= N_EN) return;

    const int mg = threadIdx.y;
    float acc[RM];
#pragma unroll
    for (int j = 0; j < RM; ++j) acc[j] = 0.f;

    const float* erow = en + (size_t)n * 128;

#pragma unroll 1
    for (int c = 0; c < 8; ++c){
        float ez[8], eZ[8];
        load8s(erow + c*8,      ez);
        load8s(erow + 64 + c*8, eZ);

#pragma unroll
        for (int j = 0; j < RM; ++j){
            float mzv[8], mZv[8];
            load8(&s_men[mg*RM + j][c*8],      mzv);   // smem broadcast
            load8(&s_men[mg*RM + j][64 + c*8], mZv);
            acc[j] += chunk_lg2(mzv, mZv, ez, eZ, C);
        }
    }

#pragma unroll
    for (int j = 0; j < RM; ++j){
        int m = m0 + mg*RM + j;
        out[(size_t)m * N_EN + n] = ex2f(acc[j] - s_gm[mg*RM + j]);
    }
}

extern "C" void kernel_launch(void* const* d_in, const int* in_sizes, int n_in,
                              void* d_out, int out_size){
    const float* men = (const float*)d_in[0];
    const float* en  = (const float*)d_in[1];
    if (n_in >= 2 && in_sizes[0] > in_sizes[1]){
        const float* t = men; men = en; en = t;
    }
    float* out = (float*)d_out;

    dim3 block(TN, MG);
    dim3 grid((N_EN + TN - 1) / TN, M_MEN / (MG * RM));
    ivr_kernel<<<grid, block>>>(men, en, out);
}